// round 13
// baseline (speedup 1.0000x reference)
#include <cuda_runtime.h>
#include <cstdint>

// Globalizer: per-point 2x2 rotation, [64, 4096, 128] f32.
// EXPERIMENT R13: bulk-granularity transfers. Each CTA moves one 32KB tile
// with cp.async.bulk (global->smem, mbarrier) computes in smem, and writes
// back with one cp.async.bulk (smem->global, bulk_group). Tests whether
// 32KB same-direction bursts beat 32B interleaved LDG/STG on DRAM
// turnaround (the remaining ~25% gap to HBM spec).

#define THREADS 256
#define TILE_F 8192                         // floats per tile = 32 KB
#define TILE_BYTES (TILE_F * 4)
#define F4_PER_TILE (TILE_F / 4)            // 2048 float4
#define F4_PER_THREAD (F4_PER_TILE / THREADS)  // 8

__global__ __launch_bounds__(THREADS) void rot2_bulk_kernel(
    const float* __restrict__ x,
    const float4* __restrict__ R,
    float* __restrict__ out)
{
    extern __shared__ float4 sbuf[];        // [0:2048) in, [2048:4096) out
    __shared__ alignas(8) uint64_t mbar;

    const size_t tile_base_f = (size_t)blockIdx.x * TILE_F;
    uint32_t s_in   = (uint32_t)__cvta_generic_to_shared(sbuf);
    uint32_t s_out  = s_in + TILE_BYTES;
    uint32_t s_mbar = (uint32_t)__cvta_generic_to_shared(&mbar);

    if (threadIdx.x == 0) {
        asm volatile("mbarrier.init.shared.b64 [%0], 1;" :: "r"(s_mbar) : "memory");
    }
    __syncthreads();

    if (threadIdx.x == 0) {
        asm volatile("mbarrier.arrive.expect_tx.shared.b64 _, [%0], %1;"
                     :: "r"(s_mbar), "r"(TILE_BYTES) : "memory");
        asm volatile("cp.async.bulk.shared::cluster.global.mbarrier::complete_tx::bytes "
                     "[%0], [%1], %2, [%3];"
                     :: "r"(s_in), "l"(x + tile_base_f), "r"(TILE_BYTES), "r"(s_mbar)
                     : "memory");
    }

    // All threads wait for the bulk load (phase parity 0).
    {
        uint32_t done = 0;
        do {
            asm volatile(
                "{\n\t.reg .pred p;\n\t"
                "mbarrier.try_wait.parity.shared.b64 p, [%1], 0;\n\t"
                "selp.b32 %0, 1, 0, p;\n\t}"
                : "=r"(done) : "r"(s_mbar) : "memory");
        } while (!done);
    }

    // Compute: conflict-free float4 (consecutive lanes -> consecutive 16B).
    const size_t tile_f4 = tile_base_f >> 2;
#pragma unroll
    for (int k = 0; k < F4_PER_THREAD; k++) {
        int idx = threadIdx.x + k * THREADS;
        float4 v = sbuf[idx];
        float4 r = __ldg(&R[(tile_f4 + idx) >> 5]);   // 32 float4 per point
        float4 o;
        o.x = fmaf(r.x, v.x, r.y * v.y);
        o.y = fmaf(r.z, v.x, r.w * v.y);
        o.z = fmaf(r.x, v.z, r.y * v.w);
        o.w = fmaf(r.z, v.z, r.w * v.w);
        sbuf[F4_PER_TILE + idx] = o;
    }
    __syncthreads();

    if (threadIdx.x == 0) {
        asm volatile("fence.proxy.async.shared::cta;" ::: "memory");
        asm volatile("cp.async.bulk.global.shared::cta.bulk_group [%0], [%1], %2;"
                     :: "l"(out + tile_base_f), "r"(s_out), "r"(TILE_BYTES)
                     : "memory");
        asm volatile("cp.async.bulk.commit_group;" ::: "memory");
        asm volatile("cp.async.bulk.wait_group 0;" ::: "memory");
    }
}

extern "C" void kernel_launch(void* const* d_in, const int* in_sizes, int n_in,
                              void* d_out, int out_size)
{
    const float*  x = (const float*)d_in[0];
    const float4* R = (const float4*)d_in[1];
    float* out = (float*)d_out;

    static bool attr_set = false;
    if (!attr_set) {
        cudaFuncSetAttribute(rot2_bulk_kernel,
                             cudaFuncAttributeMaxDynamicSharedMemorySize,
                             2 * TILE_BYTES);
        attr_set = true;
    }

    int blocks = out_size / TILE_F;     // 33,554,432 / 8192 = 4096, exact
    rot2_bulk_kernel<<<blocks, THREADS, 2 * TILE_BYTES>>>(x, R, out);
}

// round 14
// speedup vs baseline: 1.2750x; 1.2750x over previous
#include <cuda_runtime.h>

// Globalizer: per-point 2x2 rotation over a [64, 4096, 128] f32 stream.
// x:   [B, N, 128] f32 ; R: [B, N, 2, 2] f32 (r00, r01, r10, r11 per point)
// y0 = r00*x0 + r01*x1 ; y1 = r10*x0 + r11*x1 per consecutive pair.
//
// FINAL (13-round sweep, converged): HBM-bound at ~6.0 TB/s DRAM-active
// (~75% of 8 TB/s spec) -- the measured ceiling for a 1:1 interleaved
// read/write stream on this part.
//
// Winning shape: 256-bit accesses (sm_100+ ld/st.global.v8.f32), exactly
// one 32B chunk (8 floats = 4 rotated pairs) per thread. Lanes hold
// consecutive 32B chunks -> each warp instruction covers 1024B densely
// (8 full 128B lines), halving LSU/L2 request count vs 128-bit (the only
// change that measurably helped: 39.4 -> 36.1 us). 16 consecutive lanes
// share one R load (L1 broadcast). Grid divides the problem exactly
// (4,194,304 chunks = 8192 blocks x 512 threads): no bounds branch.
//
// Measured neutral-or-worse and deliberately absent: cache hints
// (.cs/.nc/.cg x4 null results), per-thread MLP batching (-15% at v4,
// -1% at v8), persistent grids (neutral), cp.async.bulk 32KB tiles (-35%:
// occupancy loss + granularity-insensitive DRAM path).

#define THREADS 512

__global__ __launch_bounds__(THREADS) void rot2_kernel(
    const float* __restrict__ x,
    const float4* __restrict__ R,
    float* __restrict__ out)
{
    int t = blockIdx.x * THREADS + threadIdx.x;

    // 128 floats per point = 16 chunks per point
    float4 r = __ldg(&R[t >> 4]);

    const float* px = x   + ((size_t)t << 3);
    float*       po = out + ((size_t)t << 3);

    float a0, a1, a2, a3, a4, a5, a6, a7;
    asm volatile(
        "ld.global.v8.f32 {%0,%1,%2,%3,%4,%5,%6,%7}, [%8];"
        : "=f"(a0), "=f"(a1), "=f"(a2), "=f"(a3),
          "=f"(a4), "=f"(a5), "=f"(a6), "=f"(a7)
        : "l"(px));

    float o0 = fmaf(r.x, a0, r.y * a1);
    float o1 = fmaf(r.z, a0, r.w * a1);
    float o2 = fmaf(r.x, a2, r.y * a3);
    float o3 = fmaf(r.z, a2, r.w * a3);
    float o4 = fmaf(r.x, a4, r.y * a5);
    float o5 = fmaf(r.z, a4, r.w * a5);
    float o6 = fmaf(r.x, a6, r.y * a7);
    float o7 = fmaf(r.z, a6, r.w * a7);

    asm volatile(
        "st.global.v8.f32 [%0], {%1,%2,%3,%4,%5,%6,%7,%8};"
        :: "l"(po),
           "f"(o0), "f"(o1), "f"(o2), "f"(o3),
           "f"(o4), "f"(o5), "f"(o6), "f"(o7)
        : "memory");
}

extern "C" void kernel_launch(void* const* d_in, const int* in_sizes, int n_in,
                              void* d_out, int out_size)
{
    const float*  x = (const float*)d_in[0];
    const float4* R = (const float4*)d_in[1];
    float* out = (float*)d_out;

    int n8 = out_size / 8;              // 4,194,304 chunks of 8 floats
    int blocks = n8 / THREADS;          // 8192, exact
    rot2_kernel<<<blocks, THREADS>>>(x, R, out);
}